// round 1
// baseline (speedup 1.0000x reference)
#include <cuda_runtime.h>
#include <cstdint>

// Problem constants
#define TOK   16384        // B*S tokens
#define HDIM  1024
#define FDIM  4096
#define NEXP  8

// GEMM tiling
#define BM 128
#define BN 128
#define BK 32
#define AST 36             // A smem row stride (BK + 4): frag banks = laneid (conflict-free)
#define BST 136            // B smem row stride (BN + 8): frag banks = 8*tg + gid (conflict-free)

// ---------------- scratch (device globals; no runtime allocation) ----------------
__device__ float g_xn[(size_t)TOK * HDIM];          //  67 MB  normalized input (fp32, tf32-roundable)
__device__ float g_h[(size_t)TOK * 2 * FDIM];       // 537 MB  relu(xn@W1+b1)-relu(b1), compact per-expert rows
__device__ float g_y[(size_t)TOK * 2 * HDIM];       // 134 MB  s_k * (h @ W2), indexed by (t*2+k)
__device__ float g_ctotal[HDIM];
__device__ float g_score[TOK * 2];
__device__ float g_stot[TOK];
__device__ int   g_cnt[NEXP];
__device__ int   g_off[NEXP];
__device__ int   g_elist[NEXP * TOK];               // entries = t*2+k

// ---------------- helpers ----------------
__device__ __forceinline__ float to_tf32(float x) {
    unsigned u;
    asm("cvt.rna.tf32.f32 %0, %1;" : "=r"(u) : "f"(x));
    return __uint_as_float(u);
}

__device__ __forceinline__ void mma_tf32(float (&d)[4], const unsigned (&a)[4], const unsigned (&b)[2]) {
    asm volatile(
        "mma.sync.aligned.m16n8k8.row.col.f32.tf32.tf32.f32 "
        "{%0,%1,%2,%3}, {%4,%5,%6,%7}, {%8,%9}, {%0,%1,%2,%3};"
        : "+f"(d[0]), "+f"(d[1]), "+f"(d[2]), "+f"(d[3])
        : "r"(a[0]), "r"(a[1]), "r"(a[2]), "r"(a[3]), "r"(b[0]), "r"(b[1]));
}

// ---------------- kernel 0: zero counters + c_total accumulator ----------------
__global__ void zero_kernel() {
    int i = threadIdx.x;             // blockDim = 1024
    if (i < NEXP) g_cnt[i] = 0;
    g_ctotal[i] = 0.f;
}

// ---------------- kernel 1: c_total[h] = sum_e relu(b1_e)@W2_e + sum_e b2_e ----------------
__global__ void ctotal_kernel(const float* __restrict__ W2,
                              const float* __restrict__ b1,
                              const float* __restrict__ b2) {
    int h = blockIdx.x * 256 + threadIdx.x;          // grid.x = 4
    int chunk = blockIdx.y;                           // grid.y = 64, 512 (e,f) pairs each
    float acc = 0.f;
    for (int i = 0; i < 512; i++) {
        int ef = chunk * 512 + i;                     // ef = e*FDIM + f
        float bb = b1[ef];
        if (bb > 0.f) acc += bb * W2[(size_t)ef * HDIM + h];
    }
    if (acc != 0.f) atomicAdd(&g_ctotal[h], acc);
    if (chunk < NEXP) atomicAdd(&g_ctotal[h], b2[chunk * HDIM + h]);
}

// ---------------- kernel 2: LayerNorm + router (softmax over 8, top-2) ----------------
__global__ void __launch_bounds__(256) ln_router_kernel(const float* __restrict__ x,
                                                        const float* __restrict__ gamma,
                                                        const float* __restrict__ beta,
                                                        const float* __restrict__ Wr,
                                                        const float* __restrict__ br) {
    const int t = blockIdx.x;
    const int tid = threadIdx.x;
    const int lane = tid & 31, wid = tid >> 5;

    const float4 xv = ((const float4*)(x + (size_t)t * HDIM))[tid];
    float s1 = xv.x + xv.y + xv.z + xv.w;
    float s2 = xv.x*xv.x + xv.y*xv.y + xv.z*xv.z + xv.w*xv.w;
    #pragma unroll
    for (int o = 16; o; o >>= 1) {
        s1 += __shfl_xor_sync(0xffffffffu, s1, o);
        s2 += __shfl_xor_sync(0xffffffffu, s2, o);
    }
    __shared__ float rs1[8], rs2[8];
    __shared__ float s_mu, s_rs;
    if (lane == 0) { rs1[wid] = s1; rs2[wid] = s2; }
    __syncthreads();
    if (wid == 0) {
        float a = (lane < 8) ? rs1[lane] : 0.f;
        float b = (lane < 8) ? rs2[lane] : 0.f;
        #pragma unroll
        for (int o = 4; o; o >>= 1) {
            a += __shfl_xor_sync(0xffffffffu, a, o);
            b += __shfl_xor_sync(0xffffffffu, b, o);
        }
        if (lane == 0) {
            float mu = a * (1.f / HDIM);
            float var = b * (1.f / HDIM) - mu * mu;
            s_mu = mu;
            s_rs = rsqrtf(var + 1e-5f);
        }
    }
    __syncthreads();
    const float mu = s_mu, rs = s_rs;

    const float4 g  = ((const float4*)gamma)[tid];
    const float4 be = ((const float4*)beta)[tid];
    float4 xn;
    xn.x = (xv.x - mu) * rs * g.x + be.x;
    xn.y = (xv.y - mu) * rs * g.y + be.y;
    xn.z = (xv.z - mu) * rs * g.z + be.z;
    xn.w = (xv.w - mu) * rs * g.w + be.w;
    ((float4*)(g_xn + (size_t)t * HDIM))[tid] = xn;

    // router logits: xn @ Wr   (Wr is [H, E] row-major)
    float lg[NEXP];
    #pragma unroll
    for (int e = 0; e < NEXP; e++) lg[e] = 0.f;
    const int h0 = tid * 4;
    const float xns[4] = {xn.x, xn.y, xn.z, xn.w};
    #pragma unroll
    for (int j = 0; j < 4; j++) {
        const float4 w0 = ((const float4*)(Wr + (size_t)(h0 + j) * NEXP))[0];
        const float4 w1 = ((const float4*)(Wr + (size_t)(h0 + j) * NEXP))[1];
        lg[0] += xns[j] * w0.x; lg[1] += xns[j] * w0.y;
        lg[2] += xns[j] * w0.z; lg[3] += xns[j] * w0.w;
        lg[4] += xns[j] * w1.x; lg[5] += xns[j] * w1.y;
        lg[6] += xns[j] * w1.z; lg[7] += xns[j] * w1.w;
    }
    #pragma unroll
    for (int e = 0; e < NEXP; e++)
        #pragma unroll
        for (int o = 16; o; o >>= 1)
            lg[e] += __shfl_xor_sync(0xffffffffu, lg[e], o);

    __shared__ float lred[8][NEXP];
    if (lane == 0)
        #pragma unroll
        for (int e = 0; e < NEXP; e++) lred[wid][e] = lg[e];
    __syncthreads();

    if (tid == 0) {
        float L[NEXP];
        #pragma unroll
        for (int e = 0; e < NEXP; e++) {
            L[e] = br[e];
            #pragma unroll
            for (int w = 0; w < 8; w++) L[e] += lred[w][e];
        }
        float mx = L[0];
        #pragma unroll
        for (int e = 1; e < NEXP; e++) mx = fmaxf(mx, L[e]);
        float ex[NEXP], den = 0.f;
        #pragma unroll
        for (int e = 0; e < NEXP; e++) { ex[e] = __expf(L[e] - mx); den += ex[e]; }
        int i0 = 0;
        #pragma unroll
        for (int e = 1; e < NEXP; e++) if (L[e] > L[i0]) i0 = e;
        int i1 = (i0 == 0) ? 1 : 0;
        #pragma unroll
        for (int e = 0; e < NEXP; e++) if (e != i0 && L[e] > L[i1]) i1 = e;
        float inv = 1.f / den;
        float sc0 = ex[i0] * inv, sc1 = ex[i1] * inv;
        g_score[2 * t]     = sc0;
        g_score[2 * t + 1] = sc1;
        g_stot[t] = sc0 + sc1;
        int p0 = atomicAdd(&g_cnt[i0], 1);
        g_elist[i0 * TOK + p0] = 2 * t;
        int p1 = atomicAdd(&g_cnt[i1], 1);
        g_elist[i1 * TOK + p1] = 2 * t + 1;
    }
}

// ---------------- kernel 3: exclusive scan of counts (E=8) ----------------
__global__ void offsets_kernel() {
    if (threadIdx.x == 0) {
        int s = 0;
        #pragma unroll
        for (int e = 0; e < NEXP; e++) { g_off[e] = s; s += g_cnt[e]; }
    }
}

// ---------------- GEMM (tf32 mma.sync), MODE 1: h = relu(xn@W1+b1)-relu(b1); MODE 2: y = s*(h@W2) ----------------
template <int MODE>
__global__ void __launch_bounds__(256, 1) gemm_kernel(const float* __restrict__ Bglob,
                                                      const float* __restrict__ bias) {
    constexpr int KDIM = (MODE == 1) ? HDIM : FDIM;
    constexpr int LDB  = (MODE == 1) ? FDIM : HDIM;
    constexpr int NDIM = (MODE == 1) ? FDIM : HDIM;
    constexpr int NKT  = KDIM / BK;

    const int e = blockIdx.z;
    const int cnt = g_cnt[e];
    const int mbase = blockIdx.y * BM;
    if (mbase >= cnt) return;
    const int nb = blockIdx.x * BN;
    const int off = g_off[e];

    extern __shared__ float sm[];
    float* As = sm;                          // 2 * BM * AST
    float* Bs = sm + 2 * BM * AST;           // 2 * BK * BST
    __shared__ int   s_rowoff[BM];
    __shared__ int   s_ent[BM];
    __shared__ float s_sc[BM];

    const int tid = threadIdx.x;
    if (tid < BM) {
        int r = mbase + tid;
        int rc = (r < cnt) ? r : (cnt - 1);
        int ent = g_elist[e * TOK + rc];
        if (MODE == 1) {
            s_rowoff[tid] = (ent >> 1) * HDIM;
        } else {
            s_rowoff[tid] = (off + rc) * FDIM;
            s_ent[tid] = ent;
            s_sc[tid]  = g_score[ent];
        }
    }
    __syncthreads();

    const float* Ag = (MODE == 1) ? g_xn : g_h;
    const float* Bptr = Bglob + (size_t)e * KDIM * NDIM + nb;

    const int arow = tid >> 3;               // 0..31 (+32/pass)
    const int acol = (tid & 7) * 4;
    const int bcol = (tid & 31) * 4;
    const int brow = tid >> 5;               // 0..7 (+8/pass)

    const int warp = tid >> 5, lane = tid & 31;
    const int wm = warp >> 2, wn = warp & 3; // warp tile 64 x 32
    const int gid = lane >> 2, tg = lane & 3;

    float acc[4][4][4];
    #pragma unroll
    for (int i = 0; i < 4; i++)
        #pragma unroll
        for (int j = 0; j < 4; j++)
            #pragma unroll
            for (int c = 0; c < 4; c++) acc[i][j][c] = 0.f;

    float4 ra[4], rb[4];

    auto load_g = [&](int k0) {
        #pragma unroll
        for (int p = 0; p < 4; p++) {
            int r = arow + p * 32;
            ra[p] = *(const float4*)(Ag + (size_t)s_rowoff[r] + k0 + acol);
            int kk = brow + p * 8;
            rb[p] = *(const float4*)(Bptr + (size_t)(k0 + kk) * LDB + bcol);
        }
    };
    auto store_s = [&](int buf) {
        float* A  = As + buf * BM * AST;
        float* Bb = Bs + buf * BK * BST;
        #pragma unroll
        for (int p = 0; p < 4; p++) {
            int r = arow + p * 32;
            float4 av = make_float4(to_tf32(ra[p].x), to_tf32(ra[p].y), to_tf32(ra[p].z), to_tf32(ra[p].w));
            *(float4*)(A + r * AST + acol) = av;
            int kk = brow + p * 8;
            float4 bv = make_float4(to_tf32(rb[p].x), to_tf32(rb[p].y), to_tf32(rb[p].z), to_tf32(rb[p].w));
            *(float4*)(Bb + kk * BST + bcol) = bv;
        }
    };
    auto compute = [&](int buf) {
        const float* A  = As + buf * BM * AST;
        const float* Bb = Bs + buf * BK * BST;
        #pragma unroll
        for (int ks = 0; ks < 4; ks++) {
            const int kb = ks * 8;
            unsigned af[4][4];
            #pragma unroll
            for (int mt = 0; mt < 4; mt++) {
                const float* ap = A + (wm * 64 + mt * 16 + gid) * AST + kb + tg;
                af[mt][0] = __float_as_uint(ap[0]);
                af[mt][2] = __float_as_uint(ap[4]);
                af[mt][1] = __float_as_uint(ap[8 * AST]);
                af[mt][3] = __float_as_uint(ap[8 * AST + 4]);
            }
            unsigned bf[4][2];
            #pragma unroll
            for (int nt = 0; nt < 4; nt++) {
                const int c = wn * 32 + nt * 8 + gid;
                bf[nt][0] = __float_as_uint(Bb[(kb + tg) * BST + c]);
                bf[nt][1] = __float_as_uint(Bb[(kb + tg + 4) * BST + c]);
            }
            #pragma unroll
            for (int mt = 0; mt < 4; mt++)
                #pragma unroll
                for (int nt = 0; nt < 4; nt++)
                    mma_tf32(acc[mt][nt], af[mt], bf[nt]);
        }
    };

    load_g(0);
    store_s(0);
    __syncthreads();
    for (int kt = 0; kt < NKT; kt++) {
        if (kt + 1 < NKT) load_g((kt + 1) * BK);
        compute(kt & 1);
        if (kt + 1 < NKT) store_s((kt + 1) & 1);
        __syncthreads();
    }

    // epilogue
    #pragma unroll
    for (int mt = 0; mt < 4; mt++) {
        #pragma unroll
        for (int pr = 0; pr < 2; pr++) {
            const int r = wm * 64 + mt * 16 + gid + pr * 8;
            if (mbase + r >= cnt) continue;
            #pragma unroll
            for (int nt = 0; nt < 4; nt++) {
                const int c  = wn * 32 + nt * 8 + 2 * tg;
                const int cg = nb + c;
                float v0 = acc[mt][nt][pr * 2 + 0];
                float v1 = acc[mt][nt][pr * 2 + 1];
                if (MODE == 1) {
                    float b0 = bias[e * FDIM + cg];
                    float b1v = bias[e * FDIM + cg + 1];
                    v0 = fmaxf(v0 + b0, 0.f) - fmaxf(b0, 0.f);
                    v1 = fmaxf(v1 + b1v, 0.f) - fmaxf(b1v, 0.f);
                    *(float2*)(g_h + (size_t)(off + mbase + r) * FDIM + cg) = make_float2(v0, v1);
                } else {
                    float s = s_sc[r];
                    *(float2*)(g_y + (size_t)s_ent[r] * HDIM + cg) = make_float2(s * v0, s * v1);
                }
            }
        }
    }
}

// ---------------- kernel 6: combine: out = x + stot*c_total + y[2t] + y[2t+1] ----------------
__global__ void __launch_bounds__(256) combine_kernel(const float* __restrict__ x, float* __restrict__ out) {
    const int t = blockIdx.x;
    const int tid = threadIdx.x;
    const float st = g_stot[t];
    const float4 xv = ((const float4*)(x + (size_t)t * HDIM))[tid];
    const float4 ct = ((const float4*)g_ctotal)[tid];
    const float4 y0 = ((const float4*)(g_y + (size_t)(2 * t) * HDIM))[tid];
    const float4 y1 = ((const float4*)(g_y + (size_t)(2 * t + 1) * HDIM))[tid];
    float4 o;
    o.x = xv.x + st * ct.x + y0.x + y1.x;
    o.y = xv.y + st * ct.y + y0.y + y1.y;
    o.z = xv.z + st * ct.z + y0.z + y1.z;
    o.w = xv.w + st * ct.w + y0.w + y1.w;
    ((float4*)(out + (size_t)t * HDIM))[tid] = o;
}

// ---------------- launch ----------------
extern "C" void kernel_launch(void* const* d_in, const int* in_sizes, int n_in,
                              void* d_out, int out_size) {
    (void)in_sizes; (void)n_in; (void)out_size;
    const float* x     = (const float*)d_in[0];
    const float* gamma = (const float*)d_in[1];
    const float* beta  = (const float*)d_in[2];
    const float* Wr    = (const float*)d_in[3];
    const float* br    = (const float*)d_in[4];
    const float* W1    = (const float*)d_in[5];
    const float* b1    = (const float*)d_in[6];
    const float* W2    = (const float*)d_in[7];
    const float* b2    = (const float*)d_in[8];
    float* out = (float*)d_out;

    const int smem = (2 * BM * AST + 2 * BK * BST) * (int)sizeof(float);  // 71680 B
    cudaFuncSetAttribute(gemm_kernel<1>, cudaFuncAttributeMaxDynamicSharedMemorySize, smem);
    cudaFuncSetAttribute(gemm_kernel<2>, cudaFuncAttributeMaxDynamicSharedMemorySize, smem);

    zero_kernel<<<1, 1024>>>();
    ctotal_kernel<<<dim3(HDIM / 256, 64), 256>>>(W2, b1, b2);
    ln_router_kernel<<<TOK, 256>>>(x, gamma, beta, Wr, br);
    offsets_kernel<<<1, 32>>>();
    gemm_kernel<1><<<dim3(FDIM / BN, TOK / BM, NEXP), 256, smem>>>(W1, b1);
    gemm_kernel<2><<<dim3(HDIM / BN, TOK / BM, NEXP), 256, smem>>>(W2, nullptr);
    combine_kernel<<<TOK, 256>>>(x, out);
}

// round 2
// speedup vs baseline: 1.0104x; 1.0104x over previous
#include <cuda_runtime.h>
#include <cstdint>

// Problem constants
#define TOK   16384        // B*S tokens
#define HDIM  1024
#define FDIM  4096
#define NEXP  8

// GEMM tiling
#define BM 128
#define BN 128
#define BK 32
#define AST 36             // A smem row stride (BK + 4): frag banks = laneid (conflict-free)
#define BST 136            // B smem row stride (BN + 8): frag banks = 8*tg + gid (conflict-free)

// ---------------- scratch (device globals; no runtime allocation) ----------------
__device__ float g_xn[(size_t)TOK * HDIM];          //  67 MB  normalized input (fp32, tf32-roundable)
__device__ float g_h[(size_t)TOK * 2 * FDIM];       // 537 MB  relu(xn@W1+b1)-relu(b1), compact per-expert rows
__device__ float g_y[(size_t)TOK * 2 * HDIM];       // 134 MB  s_k * (h @ W2), indexed by (t*2+k)
__device__ float g_ctotal[HDIM];
__device__ float g_score[TOK * 2];
__device__ float g_stot[TOK];
__device__ int   g_cnt[NEXP];
__device__ int   g_off[NEXP];
__device__ int   g_elist[NEXP * TOK];               // entries = t*2+k

// ---------------- helpers ----------------
__device__ __forceinline__ float to_tf32(float x) {
    unsigned u;
    asm("cvt.rna.tf32.f32 %0, %1;" : "=r"(u) : "f"(x));
    return __uint_as_float(u);
}

__device__ __forceinline__ void mma_tf32(float (&d)[4], const unsigned (&a)[4], const unsigned (&b)[2]) {
    asm volatile(
        "mma.sync.aligned.m16n8k8.row.col.f32.tf32.tf32.f32 "
        "{%0,%1,%2,%3}, {%4,%5,%6,%7}, {%8,%9}, {%0,%1,%2,%3};"
        : "+f"(d[0]), "+f"(d[1]), "+f"(d[2]), "+f"(d[3])
        : "r"(a[0]), "r"(a[1]), "r"(a[2]), "r"(a[3]), "r"(b[0]), "r"(b[1]));
}

// ---------------- kernel 0: zero counters + c_total accumulator ----------------
__global__ void zero_kernel() {
    int i = threadIdx.x;             // blockDim = 1024
    if (i < NEXP) g_cnt[i] = 0;
    g_ctotal[i] = 0.f;
}

// ---------------- kernel 1: c_total[h] = sum_e relu(b1_e)@W2_e + sum_e b2_e ----------------
__global__ void ctotal_kernel(const float* __restrict__ W2,
                              const float* __restrict__ b1,
                              const float* __restrict__ b2) {
    int h = blockIdx.x * 256 + threadIdx.x;          // grid.x = 4
    int chunk = blockIdx.y;                           // grid.y = 64, 512 (e,f) pairs each
    float acc = 0.f;
    for (int i = 0; i < 512; i++) {
        int ef = chunk * 512 + i;                     // ef = e*FDIM + f
        float bb = b1[ef];
        if (bb > 0.f) acc += bb * W2[(size_t)ef * HDIM + h];
    }
    if (acc != 0.f) atomicAdd(&g_ctotal[h], acc);
    if (chunk < NEXP) atomicAdd(&g_ctotal[h], b2[chunk * HDIM + h]);
}

// ---------------- kernel 2: LayerNorm + router (softmax over 8, top-2) ----------------
__global__ void __launch_bounds__(256) ln_router_kernel(const float* __restrict__ x,
                                                        const float* __restrict__ gamma,
                                                        const float* __restrict__ beta,
                                                        const float* __restrict__ Wr,
                                                        const float* __restrict__ br) {
    const int t = blockIdx.x;
    const int tid = threadIdx.x;
    const int lane = tid & 31, wid = tid >> 5;

    const float4 xv = ((const float4*)(x + (size_t)t * HDIM))[tid];
    float s1 = xv.x + xv.y + xv.z + xv.w;
    float s2 = xv.x*xv.x + xv.y*xv.y + xv.z*xv.z + xv.w*xv.w;
    #pragma unroll
    for (int o = 16; o; o >>= 1) {
        s1 += __shfl_xor_sync(0xffffffffu, s1, o);
        s2 += __shfl_xor_sync(0xffffffffu, s2, o);
    }
    __shared__ float rs1[8], rs2[8];
    __shared__ float s_mu, s_rs;
    if (lane == 0) { rs1[wid] = s1; rs2[wid] = s2; }
    __syncthreads();
    if (wid == 0) {
        float a = (lane < 8) ? rs1[lane] : 0.f;
        float b = (lane < 8) ? rs2[lane] : 0.f;
        #pragma unroll
        for (int o = 4; o; o >>= 1) {
            a += __shfl_xor_sync(0xffffffffu, a, o);
            b += __shfl_xor_sync(0xffffffffu, b, o);
        }
        if (lane == 0) {
            float mu = a * (1.f / HDIM);
            float var = b * (1.f / HDIM) - mu * mu;
            s_mu = mu;
            s_rs = rsqrtf(var + 1e-5f);
        }
    }
    __syncthreads();
    const float mu = s_mu, rs = s_rs;

    const float4 g  = ((const float4*)gamma)[tid];
    const float4 be = ((const float4*)beta)[tid];
    float4 xn;
    xn.x = (xv.x - mu) * rs * g.x + be.x;
    xn.y = (xv.y - mu) * rs * g.y + be.y;
    xn.z = (xv.z - mu) * rs * g.z + be.z;
    xn.w = (xv.w - mu) * rs * g.w + be.w;
    ((float4*)(g_xn + (size_t)t * HDIM))[tid] = xn;

    // router logits: xn @ Wr   (Wr is [H, E] row-major)
    float lg[NEXP];
    #pragma unroll
    for (int e = 0; e < NEXP; e++) lg[e] = 0.f;
    const int h0 = tid * 4;
    const float xns[4] = {xn.x, xn.y, xn.z, xn.w};
    #pragma unroll
    for (int j = 0; j < 4; j++) {
        const float4 w0 = ((const float4*)(Wr + (size_t)(h0 + j) * NEXP))[0];
        const float4 w1 = ((const float4*)(Wr + (size_t)(h0 + j) * NEXP))[1];
        lg[0] += xns[j] * w0.x; lg[1] += xns[j] * w0.y;
        lg[2] += xns[j] * w0.z; lg[3] += xns[j] * w0.w;
        lg[4] += xns[j] * w1.x; lg[5] += xns[j] * w1.y;
        lg[6] += xns[j] * w1.z; lg[7] += xns[j] * w1.w;
    }
    #pragma unroll
    for (int e = 0; e < NEXP; e++)
        #pragma unroll
        for (int o = 16; o; o >>= 1)
            lg[e] += __shfl_xor_sync(0xffffffffu, lg[e], o);

    __shared__ float lred[8][NEXP];
    if (lane == 0)
        #pragma unroll
        for (int e = 0; e < NEXP; e++) lred[wid][e] = lg[e];
    __syncthreads();

    if (tid == 0) {
        float L[NEXP];
        #pragma unroll
        for (int e = 0; e < NEXP; e++) {
            L[e] = br[e];
            #pragma unroll
            for (int w = 0; w < 8; w++) L[e] += lred[w][e];
        }
        float mx = L[0];
        #pragma unroll
        for (int e = 1; e < NEXP; e++) mx = fmaxf(mx, L[e]);
        float ex[NEXP], den = 0.f;
        #pragma unroll
        for (int e = 0; e < NEXP; e++) { ex[e] = __expf(L[e] - mx); den += ex[e]; }
        int i0 = 0;
        #pragma unroll
        for (int e = 1; e < NEXP; e++) if (L[e] > L[i0]) i0 = e;
        int i1 = (i0 == 0) ? 1 : 0;
        #pragma unroll
        for (int e = 0; e < NEXP; e++) if (e != i0 && L[e] > L[i1]) i1 = e;
        float inv = 1.f / den;
        float sc0 = ex[i0] * inv, sc1 = ex[i1] * inv;
        g_score[2 * t]     = sc0;
        g_score[2 * t + 1] = sc1;
        g_stot[t] = sc0 + sc1;
        int p0 = atomicAdd(&g_cnt[i0], 1);
        g_elist[i0 * TOK + p0] = 2 * t;
        int p1 = atomicAdd(&g_cnt[i1], 1);
        g_elist[i1 * TOK + p1] = 2 * t + 1;
    }
}

// ---------------- kernel 3: exclusive scan of counts (E=8) ----------------
__global__ void offsets_kernel() {
    if (threadIdx.x == 0) {
        int s = 0;
        #pragma unroll
        for (int e = 0; e < NEXP; e++) { g_off[e] = s; s += g_cnt[e]; }
    }
}

// ---------------- GEMM (tf32 mma.sync), MODE 1: h = relu(xn@W1+b1)-relu(b1); MODE 2: y = s*(h@W2) ----------------
template <int MODE>
__global__ void __launch_bounds__(256, 1) gemm_kernel(const float* __restrict__ Bglob,
                                                      const float* __restrict__ bias) {
    constexpr int KDIM = (MODE == 1) ? HDIM : FDIM;
    constexpr int LDB  = (MODE == 1) ? FDIM : HDIM;
    constexpr int NDIM = (MODE == 1) ? FDIM : HDIM;
    constexpr int NKT  = KDIM / BK;

    const int e = blockIdx.z;
    const int cnt = g_cnt[e];
    const int mbase = blockIdx.y * BM;
    if (mbase >= cnt) return;
    const int nb = blockIdx.x * BN;
    const int off = g_off[e];

    extern __shared__ float sm[];
    float* As = sm;                          // 2 * BM * AST
    float* Bs = sm + 2 * BM * AST;           // 2 * BK * BST
    __shared__ int   s_rowoff[BM];
    __shared__ int   s_ent[BM];
    __shared__ float s_sc[BM];

    const int tid = threadIdx.x;
    if (tid < BM) {
        int r = mbase + tid;
        int rc = (r < cnt) ? r : (cnt - 1);
        int ent = g_elist[e * TOK + rc];
        if (MODE == 1) {
            s_rowoff[tid] = (ent >> 1) * HDIM;
        } else {
            s_rowoff[tid] = (off + rc) * FDIM;
            s_ent[tid] = ent;
            s_sc[tid]  = g_score[ent];
        }
    }
    __syncthreads();

    const float* Ag = (MODE == 1) ? g_xn : g_h;
    const float* Bptr = Bglob + (size_t)e * KDIM * NDIM + nb;

    const int arow = tid >> 3;               // 0..31 (+32/pass)
    const int acol = (tid & 7) * 4;
    const int bcol = (tid & 31) * 4;
    const int brow = tid >> 5;               // 0..7 (+8/pass)

    const int warp = tid >> 5, lane = tid & 31;
    const int wm = warp >> 2, wn = warp & 3; // warp tile 64 x 32
    const int gid = lane >> 2, tg = lane & 3;

    float acc[4][4][4];
    #pragma unroll
    for (int i = 0; i < 4; i++)
        #pragma unroll
        for (int j = 0; j < 4; j++)
            #pragma unroll
            for (int c = 0; c < 4; c++) acc[i][j][c] = 0.f;

    float4 ra[4], rb[4];

    auto load_g = [&](int k0) {
        #pragma unroll
        for (int p = 0; p < 4; p++) {
            int r = arow + p * 32;
            ra[p] = *(const float4*)(Ag + (size_t)s_rowoff[r] + k0 + acol);
            int kk = brow + p * 8;
            rb[p] = *(const float4*)(Bptr + (size_t)(k0 + kk) * LDB + bcol);
        }
    };
    auto store_s = [&](int buf) {
        float* A  = As + buf * BM * AST;
        float* Bb = Bs + buf * BK * BST;
        #pragma unroll
        for (int p = 0; p < 4; p++) {
            int r = arow + p * 32;
            float4 av = make_float4(to_tf32(ra[p].x), to_tf32(ra[p].y), to_tf32(ra[p].z), to_tf32(ra[p].w));
            *(float4*)(A + r * AST + acol) = av;
            int kk = brow + p * 8;
            float4 bv = make_float4(to_tf32(rb[p].x), to_tf32(rb[p].y), to_tf32(rb[p].z), to_tf32(rb[p].w));
            *(float4*)(Bb + kk * BST + bcol) = bv;
        }
    };
    auto compute = [&](int buf) {
        const float* A  = As + buf * BM * AST;
        const float* Bb = Bs + buf * BK * BST;
        #pragma unroll
        for (int ks = 0; ks < 4; ks++) {
            const int kb = ks * 8;
            unsigned af[4][4];
            #pragma unroll
            for (int mt = 0; mt < 4; mt++) {
                const float* ap = A + (wm * 64 + mt * 16 + gid) * AST + kb + tg;
                af[mt][0] = __float_as_uint(ap[0]);
                af[mt][2] = __float_as_uint(ap[4]);
                af[mt][1] = __float_as_uint(ap[8 * AST]);
                af[mt][3] = __float_as_uint(ap[8 * AST + 4]);
            }
            unsigned bf[4][2];
            #pragma unroll
            for (int nt = 0; nt < 4; nt++) {
                const int c = wn * 32 + nt * 8 + gid;
                bf[nt][0] = __float_as_uint(Bb[(kb + tg) * BST + c]);
                bf[nt][1] = __float_as_uint(Bb[(kb + tg + 4) * BST + c]);
            }
            #pragma unroll
            for (int mt = 0; mt < 4; mt++)
                #pragma unroll
                for (int nt = 0; nt < 4; nt++)
                    mma_tf32(acc[mt][nt], af[mt], bf[nt]);
        }
    };

    load_g(0);
    store_s(0);
    __syncthreads();
    for (int kt = 0; kt < NKT; kt++) {
        if (kt + 1 < NKT) load_g((kt + 1) * BK);
        compute(kt & 1);
        if (kt + 1 < NKT) store_s((kt + 1) & 1);
        __syncthreads();
    }

    // epilogue
    #pragma unroll
    for (int mt = 0; mt < 4; mt++) {
        #pragma unroll
        for (int pr = 0; pr < 2; pr++) {
            const int r = wm * 64 + mt * 16 + gid + pr * 8;
            if (mbase + r >= cnt) continue;
            #pragma unroll
            for (int nt = 0; nt < 4; nt++) {
                const int c  = wn * 32 + nt * 8 + 2 * tg;
                const int cg = nb + c;
                float v0 = acc[mt][nt][pr * 2 + 0];
                float v1 = acc[mt][nt][pr * 2 + 1];
                if (MODE == 1) {
                    float b0 = bias[e * FDIM + cg];
                    float b1v = bias[e * FDIM + cg + 1];
                    v0 = fmaxf(v0 + b0, 0.f) - fmaxf(b0, 0.f);
                    v1 = fmaxf(v1 + b1v, 0.f) - fmaxf(b1v, 0.f);
                    *(float2*)(g_h + (size_t)(off + mbase + r) * FDIM + cg) = make_float2(v0, v1);
                } else {
                    float s = s_sc[r];
                    *(float2*)(g_y + (size_t)s_ent[r] * HDIM + cg) = make_float2(s * v0, s * v1);
                }
            }
        }
    }
}

// ---------------- kernel 6: combine: out = x + stot*c_total + y[2t] + y[2t+1] ----------------
__global__ void __launch_bounds__(256) combine_kernel(const float* __restrict__ x, float* __restrict__ out) {
    const int t = blockIdx.x;
    const int tid = threadIdx.x;
    const float st = g_stot[t];
    const float4 xv = ((const float4*)(x + (size_t)t * HDIM))[tid];
    const float4 ct = ((const float4*)g_ctotal)[tid];
    const float4 y0 = ((const float4*)(g_y + (size_t)(2 * t) * HDIM))[tid];
    const float4 y1 = ((const float4*)(g_y + (size_t)(2 * t + 1) * HDIM))[tid];
    float4 o;
    o.x = xv.x + st * ct.x + y0.x + y1.x;
    o.y = xv.y + st * ct.y + y0.y + y1.y;
    o.z = xv.z + st * ct.z + y0.z + y1.z;
    o.w = xv.w + st * ct.w + y0.w + y1.w;
    ((float4*)(out + (size_t)t * HDIM))[tid] = o;
}

// ---------------- launch ----------------
extern "C" void kernel_launch(void* const* d_in, const int* in_sizes, int n_in,
                              void* d_out, int out_size) {
    (void)in_sizes; (void)n_in; (void)out_size;
    const float* x     = (const float*)d_in[0];
    const float* gamma = (const float*)d_in[1];
    const float* beta  = (const float*)d_in[2];
    const float* Wr    = (const float*)d_in[3];
    const float* br    = (const float*)d_in[4];
    const float* W1    = (const float*)d_in[5];
    const float* b1    = (const float*)d_in[6];
    const float* W2    = (const float*)d_in[7];
    const float* b2    = (const float*)d_in[8];
    float* out = (float*)d_out;

    const int smem = (2 * BM * AST + 2 * BK * BST) * (int)sizeof(float);  // 71680 B
    cudaFuncSetAttribute(gemm_kernel<1>, cudaFuncAttributeMaxDynamicSharedMemorySize, smem);
    cudaFuncSetAttribute(gemm_kernel<2>, cudaFuncAttributeMaxDynamicSharedMemorySize, smem);

    zero_kernel<<<1, 1024>>>();
    ctotal_kernel<<<dim3(HDIM / 256, 64), 256>>>(W2, b1, b2);
    ln_router_kernel<<<TOK, 256>>>(x, gamma, beta, Wr, br);
    offsets_kernel<<<1, 32>>>();
    gemm_kernel<1><<<dim3(FDIM / BN, TOK / BM, NEXP), 256, smem>>>(W1, b1);
    gemm_kernel<2><<<dim3(HDIM / BN, TOK / BM, NEXP), 256, smem>>>(W2, nullptr);
    combine_kernel<<<TOK, 256>>>(x, out);
}